// round 4
// baseline (speedup 1.0000x reference)
#include <cuda_runtime.h>
#include <cstdint>

#define NN 50000
#define NE 600000
#define NG 64
#define D  128
#define NCLS 10
#define NT_E ((NE + 127) / 128)
#define NT_N ((NN + 127) / 128)

#define LDKB 272            // bf16 tile row stride in bytes (136 bf16)
#define LDC  132            // float stage stride (floats)

// ---- dynamic smem offsets (bytes) ----
#define SO_AH 0
#define SO_AL 34816
#define SO_W0H 69632
#define SO_W0L 104448
#define SO_W1H 139264
#define SO_W1L 174080
#define SO_C   0            // stage over A region  (128*132*4 = 67584 <= 69632)
#define SO_C2  69632        // stage over W0 region (proj tile 0)
#define SM_EDGE 139264
#define SM_BIG  208896

// ---------------- scratch (static device globals) ---------------------------
__device__ float g_edge[NE * D];
__device__ float g_node[NN * D];
__device__ float g_NW[NN * 2 * D];      // [node][NW1(128) | NW2(128)]
__device__ float g_ebar[NN * D];
__device__ float g_u[NG * D];
__device__ float g_uprojE[NG * D];
__device__ float g_uprojN[NG * D];
__device__ float g_gsum_node[NG * D];
__device__ float g_gsum_ebar[NG * D];
__device__ float g_indeg[NN];
__device__ float g_cntg[NG];
__device__ uint4 g_Wimg[5][2][2048];    // bf16 [n][k] compact images, hi/lo

// ---------------- helpers ------------------------------------------------
__device__ __forceinline__ uint32_t smem_to_u32(const void* p) {
    uint32_t a;
    asm("{ .reg .u64 t; cvta.to.shared.u64 t, %1; cvt.u32.u64 %0, t; }" : "=r"(a) : "l"(p));
    return a;
}
__device__ __forceinline__ uint32_t cvt2(float odd, float even) {
    uint32_t r;
    asm("cvt.rn.bf16x2.f32 %0, %1, %2;" : "=r"(r) : "f"(odd), "f"(even));
    return r;
}
// split 8 fp32 into bf16-hi / bf16-lo, packed 16B each
__device__ __forceinline__ void split8(const float* f, uint4& hi, uint4& lo) {
    uint32_t h[4];
    float rr[8];
#pragma unroll
    for (int q = 0; q < 4; q++) {
        h[q] = cvt2(f[2 * q + 1], f[2 * q]);
        rr[2 * q]     = f[2 * q]     - __uint_as_float(h[q] << 16);
        rr[2 * q + 1] = f[2 * q + 1] - __uint_as_float(h[q] & 0xffff0000u);
    }
    hi = make_uint4(h[0], h[1], h[2], h[3]);
    lo = make_uint4(cvt2(rr[1], rr[0]), cvt2(rr[3], rr[2]), cvt2(rr[5], rr[4]), cvt2(rr[7], rr[6]));
}
__device__ __forceinline__ void red_add_v4(float* p, float a, float b, float c, float d) {
    asm volatile("red.global.add.v4.f32 [%0], {%1,%2,%3,%4};"
                 :: "l"(p), "f"(a), "f"(b), "f"(c), "f"(d) : "memory");
}
__device__ __forceinline__ void ldm4(uint32_t addr, uint32_t r[4]) {
    asm volatile("ldmatrix.sync.aligned.m8n8.x4.shared.b16 {%0,%1,%2,%3}, [%4];"
                 : "=r"(r[0]), "=r"(r[1]), "=r"(r[2]), "=r"(r[3]) : "r"(addr));
}
__device__ __forceinline__ void mma16816(float c[4], const uint32_t a[4], uint32_t b0, uint32_t b1) {
    asm volatile("mma.sync.aligned.m16n8k16.row.col.f32.bf16.bf16.f32 "
                 "{%0,%1,%2,%3}, {%4,%5,%6,%7}, {%8,%9}, {%0,%1,%2,%3};"
                 : "+f"(c[0]), "+f"(c[1]), "+f"(c[2]), "+f"(c[3])
                 : "r"(a[0]), "r"(a[1]), "r"(a[2]), "r"(a[3]), "r"(b0), "r"(b1));
}

// one 128x128x128 bf16 term: acc += A(smem sA) @ B(smem sB)^T
__device__ __forceinline__ void mma_term(uint32_t sA, uint32_t sB,
                                         float acc[4][4][4], int lane, int wm, int wn)
{
    uint32_t aBase = sA + (uint32_t)((wm * 64 + (lane & 7) + ((lane >> 3) & 1) * 8) * LDKB
                                     + ((lane >> 4) & 1) * 16);
    uint32_t bBase = sB + (uint32_t)((wn * 32 + (lane & 7) + ((lane >> 4) & 1) * 8) * LDKB
                                     + ((lane >> 3) & 1) * 16);
#pragma unroll
    for (int ks = 0; ks < 8; ks++) {
        uint32_t a[4][4], b[2][4];
#pragma unroll
        for (int mf = 0; mf < 4; mf++) ldm4(aBase + mf * 16 * LDKB + ks * 32, a[mf]);
#pragma unroll
        for (int np = 0; np < 2; np++) ldm4(bBase + np * 16 * LDKB + ks * 32, b[np]);
#pragma unroll
        for (int mf = 0; mf < 4; mf++)
#pragma unroll
            for (int nf = 0; nf < 4; nf++)
                mma16816(acc[mf][nf], a[mf], b[nf >> 1][(nf & 1) * 2], b[nf >> 1][(nf & 1) * 2 + 1]);
    }
}
__device__ __forceinline__ void acc_zero(float acc[4][4][4]) {
#pragma unroll
    for (int i = 0; i < 4; i++)
#pragma unroll
        for (int j = 0; j < 4; j++)
#pragma unroll
            for (int q = 0; q < 4; q++) acc[i][j][q] = 0.f;
}
__device__ __forceinline__ void stage_acc(float* smC, const float acc[4][4][4],
                                          int lane, int wm, int wn)
{
    int qr = lane >> 2, qc = (lane & 3) * 2;
#pragma unroll
    for (int mf = 0; mf < 4; mf++)
#pragma unroll
        for (int nf = 0; nf < 4; nf++) {
            float* p = smC + (wm * 64 + mf * 16 + qr) * LDC + wn * 32 + nf * 8 + qc;
            p[0] = acc[mf][nf][0];
            p[1] = acc[mf][nf][1];
            p[8 * LDC] = acc[mf][nf][2];
            p[8 * LDC + 1] = acc[mf][nf][3];
        }
}
// copy one precomputed W image (hi+lo) into padded smem tiles
__device__ __forceinline__ void copy_w(char* sm, int so_h, int so_l, int m, int t)
{
    const uint4* sh = g_Wimg[m][0];
    const uint4* sl = g_Wimg[m][1];
    for (int i = t; i < 2048; i += 256) {
        int dst = (i >> 4) * LDKB + (i & 15) * 16;
        *(uint4*)(sm + so_h + dst) = sh[i];
        *(uint4*)(sm + so_l + dst) = sl[i];
    }
}

// ---------------- small kernels ----------------------------------------------
__global__ void k_init(const float* __restrict__ u_in)
{
    int i = blockIdx.x * blockDim.x + threadIdx.x;
    if (i < NN) g_indeg[i] = 0.f;
    if (i < NG) g_cntg[i] = 0.f;
    if (i < NG * D) g_u[i] = u_in[i];
}
__global__ void k_hist(const int* __restrict__ ei, const int* __restrict__ batch)
{
    int i = blockIdx.x * blockDim.x + threadIdx.x;
    if (i < NE) atomicAdd(&g_indeg[ei[NE + i]], 1.f);
    if (i < NN) atomicAdd(&g_cntg[batch[i]], 1.f);
}
__global__ void k_zero_pass()
{
    int i = blockIdx.x * blockDim.x + threadIdx.x;
    int stride = gridDim.x * blockDim.x;
    for (int x = i; x < NN * D; x += stride) g_ebar[x] = 0.f;
    if (i < NG * D) { g_gsum_node[i] = 0.f; g_gsum_ebar[i] = 0.f; }
}
// build bf16 hi/lo compact [n][k] images of Wᵀ: B[n][k] = W[k][n]
__global__ void k_wprep(const float* __restrict__ We_w, const float* __restrict__ Wn_w)
{
    int m = blockIdx.x, t = threadIdx.x;
    const float* W = (m == 0) ? We_w
                   : (m == 1) ? We_w + D * D
                   : (m == 2) ? We_w + 2 * D * D
                   : (m == 3) ? Wn_w
                              : Wn_w + D * D;
    uint4* ih = g_Wimg[m][0];
    uint4* il = g_Wimg[m][1];
    for (int g = t; g < 2048; g += 256) {
        int n = g >> 4, c8 = (g & 15) << 3;
        float f[8];
#pragma unroll
        for (int j = 0; j < 8; j++) f[j] = W[(c8 + j) * D + n];
        uint4 hi, lo;
        split8(f, hi, lo);
        ih[g] = hi;
        il[g] = lo;
    }
}
__global__ void k_uproj(const float* __restrict__ We_w, const float* __restrict__ We_b,
                        const float* __restrict__ Wn_w, const float* __restrict__ Wn_b)
{
    int g = blockIdx.x, j = threadIdx.x;
    __shared__ float us[D];
    us[j] = g_u[g * D + j];
    __syncthreads();
    float aE = We_b[j], aN = Wn_b[j];
#pragma unroll 4
    for (int k = 0; k < D; k++) {
        float uv = us[k];
        aE = fmaf(uv, We_w[(3 * D + k) * D + j], aE);
        aN = fmaf(uv, Wn_w[(2 * D + k) * D + j], aN);
    }
    g_uprojE[g * D + j] = aE;
    g_uprojN[g * D + j] = aN;
}

// ---------------- node projections: NW1|NW2 = node @ [We1|We2] ---------------
__global__ void __launch_bounds__(256, 1) k_proj(const float* __restrict__ Nsrc)
{
    extern __shared__ char sm[];
    uint32_t smb = smem_to_u32(sm);
    int t = threadIdx.x, lane = t & 31, wid = t >> 5;
    int wm = wid >> 2, wn = wid & 3;
    int n0 = blockIdx.x * 128;

    copy_w(sm, SO_W0H, SO_W0L, 0, t);   // We1
    copy_w(sm, SO_W1H, SO_W1L, 1, t);   // We2
    for (int g = t; g < 2048; g += 256) {
        int r = g >> 4, c8 = (g & 15) << 3;
        int n = n0 + r;
        float f[8] = {0, 0, 0, 0, 0, 0, 0, 0};
        if (n < NN) { *(float4*)f = *(const float4*)(Nsrc + (size_t)n * D + c8);
                      *(float4*)(f + 4) = *(const float4*)(Nsrc + (size_t)n * D + c8 + 4); }
        uint4 hi, lo; split8(f, hi, lo);
        int off = r * LDKB + c8 * 2;
        *(uint4*)(sm + SO_AH + off) = hi;
        *(uint4*)(sm + SO_AL + off) = lo;
    }
    __syncthreads();

    float acc[4][4][4];
    // tile 0: node @ We1
    acc_zero(acc);
    mma_term(smb + SO_AH, smb + SO_W0H, acc, lane, wm, wn);
    mma_term(smb + SO_AH, smb + SO_W0L, acc, lane, wm, wn);
    mma_term(smb + SO_AL, smb + SO_W0H, acc, lane, wm, wn);
    __syncthreads();                         // all warps done reading W0
    stage_acc((float*)(sm + SO_C2), acc, lane, wm, wn);
    __syncthreads();
    {
        int r = t >> 1, hh = t & 1;
        int n = n0 + r;
        if (n < NN) {
            const float* src = (const float*)(sm + SO_C2) + r * LDC + hh * 64;
            float* dst = g_NW + (size_t)n * 256 + hh * 64;
#pragma unroll
            for (int j = 0; j < 16; j++) *(float4*)(dst + 4 * j) = *(const float4*)(src + 4 * j);
        }
    }
    // tile 1: node @ We2 (A and W1 untouched)
    acc_zero(acc);
    mma_term(smb + SO_AH, smb + SO_W1H, acc, lane, wm, wn);
    mma_term(smb + SO_AH, smb + SO_W1L, acc, lane, wm, wn);
    mma_term(smb + SO_AL, smb + SO_W1H, acc, lane, wm, wn);
    __syncthreads();                         // all warps done reading A
    stage_acc((float*)(sm + SO_C), acc, lane, wm, wn);
    __syncthreads();
    {
        int r = t >> 1, hh = t & 1;
        int n = n0 + r;
        if (n < NN) {
            const float* src = (const float*)(sm + SO_C) + r * LDC + hh * 64;
            float* dst = g_NW + (size_t)n * 256 + 128 + hh * 64;
#pragma unroll
            for (int j = 0; j < 16; j++) *(float4*)(dst + 4 * j) = *(const float4*)(src + 4 * j);
        }
    }
}

// ---------------- edge update: relu(e@We3 + NW1[src] + NW2[dst] + uprojE) ----
__global__ void __launch_bounds__(256, 1) k_edge_tc(const float* __restrict__ Eattr,
                                                    const int* __restrict__ ei,
                                                    const int* __restrict__ batch, int last)
{
    extern __shared__ char sm[];
    uint32_t smb = smem_to_u32(sm);
    int t = threadIdx.x, lane = t & 31, wid = t >> 5;
    int wm = wid >> 2, wn = wid & 3;
    int e0 = blockIdx.x * 128;

    copy_w(sm, SO_W0H, SO_W0L, 2, t);   // We3
    for (int g = t; g < 2048; g += 256) {
        int r = g >> 4, c8 = (g & 15) << 3;
        int e = e0 + r;
        float f[8] = {0, 0, 0, 0, 0, 0, 0, 0};
        if (e < NE) { *(float4*)f = *(const float4*)(Eattr + (size_t)e * D + c8);
                      *(float4*)(f + 4) = *(const float4*)(Eattr + (size_t)e * D + c8 + 4); }
        uint4 hi, lo; split8(f, hi, lo);
        int off = r * LDKB + c8 * 2;
        *(uint4*)(sm + SO_AH + off) = hi;
        *(uint4*)(sm + SO_AL + off) = lo;
    }
    __syncthreads();

    float acc[4][4][4];
    acc_zero(acc);
    mma_term(smb + SO_AH, smb + SO_W0H, acc, lane, wm, wn);
    mma_term(smb + SO_AH, smb + SO_W0L, acc, lane, wm, wn);
    mma_term(smb + SO_AL, smb + SO_W0H, acc, lane, wm, wn);
    __syncthreads();
    stage_acc((float*)(sm + SO_C), acc, lane, wm, wn);
    __syncthreads();

    int r = t >> 1, hh = t & 1;
    int e = e0 + r;
    if (e < NE) {
        int sN = ei[e], dN = ei[NE + e], gb = batch[sN];
        const float* sc = (const float*)(sm + SO_C) + r * LDC + hh * 64;
        const float* ps = g_NW + (size_t)sN * 256 + hh * 64;
        const float* pd = g_NW + (size_t)dN * 256 + 128 + hh * 64;
        const float* pu = g_uprojE + (size_t)gb * D + hh * 64;
        float* pe = g_edge + (size_t)e * D + hh * 64;
        float* pb = g_ebar + (size_t)dN * D + hh * 64;
#pragma unroll
        for (int j = 0; j < 16; j++) {
            float4 c = *(const float4*)(sc + 4 * j);
            float4 a = *(const float4*)(ps + 4 * j);
            float4 b = *(const float4*)(pd + 4 * j);
            float4 u = *(const float4*)(pu + 4 * j);
            float y0 = fmaxf(c.x + a.x + b.x + u.x, 0.f);
            float y1 = fmaxf(c.y + a.y + b.y + u.y, 0.f);
            float y2 = fmaxf(c.z + a.z + b.z + u.z, 0.f);
            float y3 = fmaxf(c.w + a.w + b.w + u.w, 0.f);
            if (!last) *(float4*)(pe + 4 * j) = make_float4(y0, y1, y2, y3);
            red_add_v4(pb + 4 * j, y0, y1, y2, y3);
        }
    }
}

// ---------------- node update: relu(node@Wn1 + ebar@Wn2 + uprojN) -------------
__global__ void __launch_bounds__(256, 1) k_node_tc(const float* __restrict__ Nsrc,
                                                    const int* __restrict__ batch, int last)
{
    extern __shared__ char sm[];
    uint32_t smb = smem_to_u32(sm);
    int t = threadIdx.x, lane = t & 31, wid = t >> 5;
    int wm = wid >> 2, wn = wid & 3;
    int n0 = blockIdx.x * 128;

    copy_w(sm, SO_W0H, SO_W0L, 3, t);   // Wn1
    copy_w(sm, SO_W1H, SO_W1L, 4, t);   // Wn2

    // phase 1: A = ebar * inv_deg (+ per-graph ebar sums)
    for (int g = t; g < 2048; g += 256) {
        int r = g >> 4, c8 = (g & 15) << 3;
        int n = n0 + r;
        float f[8] = {0, 0, 0, 0, 0, 0, 0, 0};
        if (n < NN) {
            float inv = 1.f / fmaxf(g_indeg[n], 1.f);
            float4 v0 = *(const float4*)(g_ebar + (size_t)n * D + c8);
            float4 v1 = *(const float4*)(g_ebar + (size_t)n * D + c8 + 4);
            f[0] = v0.x * inv; f[1] = v0.y * inv; f[2] = v0.z * inv; f[3] = v0.w * inv;
            f[4] = v1.x * inv; f[5] = v1.y * inv; f[6] = v1.z * inv; f[7] = v1.w * inv;
            float* pg = g_gsum_ebar + (size_t)batch[n] * D + c8;
            red_add_v4(pg,     f[0], f[1], f[2], f[3]);
            red_add_v4(pg + 4, f[4], f[5], f[6], f[7]);
        }
        uint4 hi, lo; split8(f, hi, lo);
        int off = r * LDKB + c8 * 2;
        *(uint4*)(sm + SO_AH + off) = hi;
        *(uint4*)(sm + SO_AL + off) = lo;
    }
    __syncthreads();

    float acc[4][4][4];
    acc_zero(acc);
    mma_term(smb + SO_AH, smb + SO_W1H, acc, lane, wm, wn);   // ebar @ Wn2
    mma_term(smb + SO_AH, smb + SO_W1L, acc, lane, wm, wn);
    mma_term(smb + SO_AL, smb + SO_W1H, acc, lane, wm, wn);
    __syncthreads();                     // all warps done reading A

    // phase 2: A = node features, accumulate node @ Wn1
    for (int g = t; g < 2048; g += 256) {
        int r = g >> 4, c8 = (g & 15) << 3;
        int n = n0 + r;
        float f[8] = {0, 0, 0, 0, 0, 0, 0, 0};
        if (n < NN) { *(float4*)f = *(const float4*)(Nsrc + (size_t)n * D + c8);
                      *(float4*)(f + 4) = *(const float4*)(Nsrc + (size_t)n * D + c8 + 4); }
        uint4 hi, lo; split8(f, hi, lo);
        int off = r * LDKB + c8 * 2;
        *(uint4*)(sm + SO_AH + off) = hi;
        *(uint4*)(sm + SO_AL + off) = lo;
    }
    __syncthreads();
    mma_term(smb + SO_AH, smb + SO_W0H, acc, lane, wm, wn);   // + node @ Wn1
    mma_term(smb + SO_AH, smb + SO_W0L, acc, lane, wm, wn);
    mma_term(smb + SO_AL, smb + SO_W0H, acc, lane, wm, wn);
    __syncthreads();
    stage_acc((float*)(sm + SO_C), acc, lane, wm, wn);
    __syncthreads();

    int r = t >> 1, hh = t & 1;
    int n = n0 + r;
    if (n < NN) {
        int gb = batch[n];
        const float* sc = (const float*)(sm + SO_C) + r * LDC + hh * 64;
        const float* pu = g_uprojN + (size_t)gb * D + hh * 64;
        float* pn = g_node + (size_t)n * D + hh * 64;
        float* pg = g_gsum_node + (size_t)gb * D + hh * 64;
#pragma unroll
        for (int j = 0; j < 16; j++) {
            float4 c = *(const float4*)(sc + 4 * j);
            float4 u = *(const float4*)(pu + 4 * j);
            float y0 = fmaxf(c.x + u.x, 0.f);
            float y1 = fmaxf(c.y + u.y, 0.f);
            float y2 = fmaxf(c.z + u.z, 0.f);
            float y3 = fmaxf(c.w + u.w, 0.f);
            if (!last) *(float4*)(pn + 4 * j) = make_float4(y0, y1, y2, y3);
            red_add_v4(pg + 4 * j, y0, y1, y2, y3);
        }
    }
}

// ---------------- global update + next-pass u projections ---------------------
__global__ void k_global(const float* __restrict__ Wg_w, const float* __restrict__ Wg_b,
                         const float* __restrict__ We_w, const float* __restrict__ We_b,
                         const float* __restrict__ Wn_w, const float* __restrict__ Wn_b)
{
    int g = blockIdx.x, j = threadIdx.x;
    __shared__ float nm[D], em[D], uu[D], un[D];
    float inv = 1.f / fmaxf(g_cntg[g], 1.f);
    nm[j] = g_gsum_node[g * D + j] * inv;
    em[j] = g_gsum_ebar[g * D + j] * inv;
    uu[j] = g_u[g * D + j];
    __syncthreads();
    float acc = Wg_b[j];
#pragma unroll 4
    for (int k = 0; k < D; k++) {
        acc = fmaf(nm[k], Wg_w[k * D + j], acc);
        acc = fmaf(em[k], Wg_w[(D + k) * D + j], acc);
        acc = fmaf(uu[k], Wg_w[(2 * D + k) * D + j], acc);
    }
    float r = fmaxf(acc, 0.f);
    g_u[g * D + j] = r;
    un[j] = r;
    __syncthreads();
    float aE = We_b[j], aN = Wn_b[j];
#pragma unroll 4
    for (int k = 0; k < D; k++) {
        float uv = un[k];
        aE = fmaf(uv, We_w[(3 * D + k) * D + j], aE);
        aN = fmaf(uv, Wn_w[(2 * D + k) * D + j], aN);
    }
    g_uprojE[g * D + j] = aE;
    g_uprojN[g * D + j] = aN;
}

__global__ void k_readout(const float* __restrict__ lin_w, const float* __restrict__ lin_b,
                          float* __restrict__ out)
{
    int g = blockIdx.x, t = threadIdx.x;
    __shared__ float pooled[3 * D];
    float inv = 1.f / fmaxf(g_cntg[g], 1.f);
    pooled[t]         = g_gsum_node[g * D + t] * inv;
    pooled[D + t]     = g_gsum_ebar[g * D + t] * inv;
    pooled[2 * D + t] = g_u[g * D + t];
    __syncthreads();
    if (t < NCLS) {
        float acc = lin_b[t];
#pragma unroll 4
        for (int k = 0; k < 3 * D; k++) acc = fmaf(pooled[k], lin_w[k * NCLS + t], acc);
        out[g * NCLS + t] = acc;
    }
}

// ---------------- host launcher ----------------------------------------------
extern "C" void kernel_launch(void* const* d_in, const int* in_sizes, int n_in,
                              void* d_out, int out_size)
{
    const float* node_in = (const float*)d_in[0];
    const float* edge_in = (const float*)d_in[1];
    const float* u_in    = (const float*)d_in[2];
    const int*   ei      = (const int*)d_in[3];
    const int*   batch   = (const int*)d_in[4];
    const float* We_w = (const float*)d_in[5];
    const float* We_b = (const float*)d_in[6];
    const float* Wn_w = (const float*)d_in[7];
    const float* Wn_b = (const float*)d_in[8];
    const float* Wg_w = (const float*)d_in[9];
    const float* Wg_b = (const float*)d_in[10];
    const float* lin_w = (const float*)d_in[11];
    const float* lin_b = (const float*)d_in[12];
    float* out = (float*)d_out;

    float *p_node = nullptr, *p_edge = nullptr;
    cudaGetSymbolAddress((void**)&p_node, g_node);
    cudaGetSymbolAddress((void**)&p_edge, g_edge);

    cudaFuncSetAttribute(k_proj,    cudaFuncAttributeMaxDynamicSharedMemorySize, SM_BIG);
    cudaFuncSetAttribute(k_edge_tc, cudaFuncAttributeMaxDynamicSharedMemorySize, SM_EDGE);
    cudaFuncSetAttribute(k_node_tc, cudaFuncAttributeMaxDynamicSharedMemorySize, SM_BIG);

    k_init<<<(NN + 255) / 256, 256>>>(u_in);
    k_hist<<<(NE + 255) / 256, 256>>>(ei, batch);
    k_wprep<<<5, 256>>>(We_w, Wn_w);
    k_uproj<<<NG, D>>>(We_w, We_b, Wn_w, Wn_b);

    const float* nsrc = node_in;
    const float* esrc = edge_in;
    for (int p = 0; p < 3; p++) {
        int last = (p == 2);
        k_zero_pass<<<1024, 256>>>();
        k_proj<<<NT_N, 256, SM_BIG>>>(nsrc);
        k_edge_tc<<<NT_E, 256, SM_EDGE>>>(esrc, ei, batch, last);
        k_node_tc<<<NT_N, 256, SM_BIG>>>(nsrc, batch, last);
        k_global<<<NG, D>>>(Wg_w, Wg_b, We_w, We_b, Wn_w, Wn_b);
        nsrc = p_node;
        esrc = p_edge;
    }
    k_readout<<<NG, D>>>(lin_w, lin_b, out);
}

// round 5
// speedup vs baseline: 1.3623x; 1.3623x over previous
#include <cuda_runtime.h>
#include <cstdint>

#define NN 50000
#define NE 600000
#define NG 64
#define D  128
#define NCLS 10
#define NT_E  (NE / 64)            // 9375 (exact)
#define NT64_N ((NN + 63) / 64)    // 782
#define NT_N  ((NN + 127) / 128)   // 391 (proj)

#define LDKB 272                   // bf16 tile row stride in bytes
#define LDC  132                   // float stage stride (floats)

// ---- 64-row kernel smem map (bytes), total 104448 -> 2 CTAs/SM ----
#define SO64_AH 0
#define SO64_AL 17408
#define SO64_WH 34816
#define SO64_WL 69632
#define SM64    104448

// ---- 128-row proj kernel smem map, total 208896 -> 1 CTA/SM ----
#define SO_AH 0
#define SO_AL 34816
#define SO_W0H 69632
#define SO_W0L 104448
#define SO_W1H 139264
#define SO_W1L 174080
#define SO_C   0                   // stage over A region
#define SO_C2  69632               // stage over W0 region
#define SM_BIG 208896

// ---------------- scratch (static device globals) ---------------------------
__device__ float g_edge[NE * D];
__device__ float g_node[NN * D];
__device__ float g_NW[NN * 2 * D];      // [node][NW1(128) | NW2(128)]
__device__ float g_tmp[NN * D];         // ebar @ Wn2 partial
__device__ float g_ebar[NN * D];
__device__ float g_u[NG * D];
__device__ float g_uprojE[NG * D];
__device__ float g_uprojN[NG * D];
__device__ float g_gsum_node[NG * D];
__device__ float g_gsum_ebar[NG * D];
__device__ float g_indeg[NN];
__device__ float g_cntg[NG];
__device__ uint4 g_Wimg[5][2][2048];    // bf16 [n][k] compact images, hi/lo

// ---------------- helpers ------------------------------------------------
__device__ __forceinline__ uint32_t smem_to_u32(const void* p) {
    uint32_t a;
    asm("{ .reg .u64 t; cvta.to.shared.u64 t, %1; cvt.u32.u64 %0, t; }" : "=r"(a) : "l"(p));
    return a;
}
__device__ __forceinline__ uint32_t cvt2(float odd, float even) {
    uint32_t r;
    asm("cvt.rn.bf16x2.f32 %0, %1, %2;" : "=r"(r) : "f"(odd), "f"(even));
    return r;
}
__device__ __forceinline__ void split8(const float* f, uint4& hi, uint4& lo) {
    uint32_t h[4];
    float rr[8];
#pragma unroll
    for (int q = 0; q < 4; q++) {
        h[q] = cvt2(f[2 * q + 1], f[2 * q]);
        rr[2 * q]     = f[2 * q]     - __uint_as_float(h[q] << 16);
        rr[2 * q + 1] = f[2 * q + 1] - __uint_as_float(h[q] & 0xffff0000u);
    }
    hi = make_uint4(h[0], h[1], h[2], h[3]);
    lo = make_uint4(cvt2(rr[1], rr[0]), cvt2(rr[3], rr[2]), cvt2(rr[5], rr[4]), cvt2(rr[7], rr[6]));
}
__device__ __forceinline__ void red_add_v4(float* p, float a, float b, float c, float d) {
    asm volatile("red.global.add.v4.f32 [%0], {%1,%2,%3,%4};"
                 :: "l"(p), "f"(a), "f"(b), "f"(c), "f"(d) : "memory");
}
__device__ __forceinline__ void ldm4(uint32_t addr, uint32_t r[4]) {
    asm volatile("ldmatrix.sync.aligned.m8n8.x4.shared.b16 {%0,%1,%2,%3}, [%4];"
                 : "=r"(r[0]), "=r"(r[1]), "=r"(r[2]), "=r"(r[3]) : "r"(addr));
}
__device__ __forceinline__ void mma16816(float c[4], const uint32_t a[4], uint32_t b0, uint32_t b1) {
    asm volatile("mma.sync.aligned.m16n8k16.row.col.f32.bf16.bf16.f32 "
                 "{%0,%1,%2,%3}, {%4,%5,%6,%7}, {%8,%9}, {%0,%1,%2,%3};"
                 : "+f"(c[0]), "+f"(c[1]), "+f"(c[2]), "+f"(c[3])
                 : "r"(a[0]), "r"(a[1]), "r"(a[2]), "r"(a[3]), "r"(b0), "r"(b1));
}

// ============ 64-row GEMM engine: 128 threads, 4 warps (2m x 2n) ============
// C[64,128] = Ah@Wh + Al@Wh + Ah@Wl  (bf16 split, fp32 acc)
__device__ __forceinline__ void mainloop64(uint32_t smb, float acc[2][8][4], int lane, int wm, int wn)
{
    uint32_t aoff = (uint32_t)((wm * 32 + (lane & 7) + ((lane >> 3) & 1) * 8) * LDKB
                               + ((lane >> 4) & 1) * 16);
    uint32_t boff = (uint32_t)((wn * 64 + (lane & 7) + ((lane >> 4) & 1) * 8) * LDKB
                               + ((lane >> 3) & 1) * 16);
    uint32_t aH = smb + SO64_AH + aoff;
    uint32_t aL = smb + SO64_AL + aoff;
    uint32_t bH = smb + SO64_WH + boff;
    uint32_t bL = smb + SO64_WL + boff;
#pragma unroll
    for (int ks = 0; ks < 8; ks++) {
        uint32_t ah[2][4], al[2][4], b[4][4];
#pragma unroll
        for (int mf = 0; mf < 2; mf++) {
            ldm4(aH + mf * 16 * LDKB + ks * 32, ah[mf]);
            ldm4(aL + mf * 16 * LDKB + ks * 32, al[mf]);
        }
#pragma unroll
        for (int np = 0; np < 4; np++) ldm4(bH + np * 16 * LDKB + ks * 32, b[np]);
#pragma unroll
        for (int mf = 0; mf < 2; mf++)
#pragma unroll
            for (int np = 0; np < 4; np++) {
                mma16816(acc[mf][np * 2],     ah[mf], b[np][0], b[np][1]);
                mma16816(acc[mf][np * 2 + 1], ah[mf], b[np][2], b[np][3]);
            }
#pragma unroll
        for (int mf = 0; mf < 2; mf++)
#pragma unroll
            for (int np = 0; np < 4; np++) {
                mma16816(acc[mf][np * 2],     al[mf], b[np][0], b[np][1]);
                mma16816(acc[mf][np * 2 + 1], al[mf], b[np][2], b[np][3]);
            }
#pragma unroll
        for (int np = 0; np < 4; np++) ldm4(bL + np * 16 * LDKB + ks * 32, b[np]);
#pragma unroll
        for (int mf = 0; mf < 2; mf++)
#pragma unroll
            for (int np = 0; np < 4; np++) {
                mma16816(acc[mf][np * 2],     ah[mf], b[np][0], b[np][1]);
                mma16816(acc[mf][np * 2 + 1], ah[mf], b[np][2], b[np][3]);
            }
    }
}
__device__ __forceinline__ void acc_zero64(float acc[2][8][4]) {
#pragma unroll
    for (int i = 0; i < 2; i++)
#pragma unroll
        for (int j = 0; j < 8; j++)
#pragma unroll
            for (int q = 0; q < 4; q++) acc[i][j][q] = 0.f;
}
__device__ __forceinline__ void stage64(float* smC, const float acc[2][8][4],
                                        int lane, int wm, int wn)
{
    int qr = lane >> 2, qc = (lane & 3) * 2;
#pragma unroll
    for (int mf = 0; mf < 2; mf++)
#pragma unroll
        for (int nf = 0; nf < 8; nf++) {
            float* p = smC + (wm * 32 + mf * 16 + qr) * LDC + wn * 64 + nf * 8 + qc;
            p[0] = acc[mf][nf][0];
            p[1] = acc[mf][nf][1];
            p[8 * LDC] = acc[mf][nf][2];
            p[8 * LDC + 1] = acc[mf][nf][3];
        }
}
__device__ __forceinline__ void copy_w64(char* sm, int m, int t)
{
    const uint4* sh = g_Wimg[m][0];
    const uint4* sl = g_Wimg[m][1];
#pragma unroll
    for (int i = t; i < 2048; i += 128) {
        int dst = (i >> 4) * LDKB + (i & 15) * 16;
        *(uint4*)(sm + SO64_WH + dst) = sh[i];
        *(uint4*)(sm + SO64_WL + dst) = sl[i];
    }
}
__device__ __forceinline__ void store_a64(char* sm, int r, int c8, const float* f)
{
    uint4 hi, lo; split8(f, hi, lo);
    int off = r * LDKB + c8 * 2;
    *(uint4*)(sm + SO64_AH + off) = hi;
    *(uint4*)(sm + SO64_AL + off) = lo;
}

// ============ 128-row proj engine (8 warps, 2m x 4n), from round 4 ==========
__device__ __forceinline__ void mma_term(uint32_t sA, uint32_t sB,
                                         float acc[4][4][4], int lane, int wm, int wn)
{
    uint32_t aBase = sA + (uint32_t)((wm * 64 + (lane & 7) + ((lane >> 3) & 1) * 8) * LDKB
                                     + ((lane >> 4) & 1) * 16);
    uint32_t bBase = sB + (uint32_t)((wn * 32 + (lane & 7) + ((lane >> 4) & 1) * 8) * LDKB
                                     + ((lane >> 3) & 1) * 16);
#pragma unroll
    for (int ks = 0; ks < 8; ks++) {
        uint32_t a[4][4], b[2][4];
#pragma unroll
        for (int mf = 0; mf < 4; mf++) ldm4(aBase + mf * 16 * LDKB + ks * 32, a[mf]);
#pragma unroll
        for (int np = 0; np < 2; np++) ldm4(bBase + np * 16 * LDKB + ks * 32, b[np]);
#pragma unroll
        for (int mf = 0; mf < 4; mf++)
#pragma unroll
            for (int nf = 0; nf < 4; nf++)
                mma16816(acc[mf][nf], a[mf], b[nf >> 1][(nf & 1) * 2], b[nf >> 1][(nf & 1) * 2 + 1]);
    }
}
__device__ __forceinline__ void acc_zero(float acc[4][4][4]) {
#pragma unroll
    for (int i = 0; i < 4; i++)
#pragma unroll
        for (int j = 0; j < 4; j++)
#pragma unroll
            for (int q = 0; q < 4; q++) acc[i][j][q] = 0.f;
}
__device__ __forceinline__ void stage_acc(float* smC, const float acc[4][4][4],
                                          int lane, int wm, int wn)
{
    int qr = lane >> 2, qc = (lane & 3) * 2;
#pragma unroll
    for (int mf = 0; mf < 4; mf++)
#pragma unroll
        for (int nf = 0; nf < 4; nf++) {
            float* p = smC + (wm * 64 + mf * 16 + qr) * LDC + wn * 32 + nf * 8 + qc;
            p[0] = acc[mf][nf][0];
            p[1] = acc[mf][nf][1];
            p[8 * LDC] = acc[mf][nf][2];
            p[8 * LDC + 1] = acc[mf][nf][3];
        }
}
__device__ __forceinline__ void copy_w128(char* sm, int so_h, int so_l, int m, int t)
{
    const uint4* sh = g_Wimg[m][0];
    const uint4* sl = g_Wimg[m][1];
#pragma unroll
    for (int i = t; i < 2048; i += 256) {
        int dst = (i >> 4) * LDKB + (i & 15) * 16;
        *(uint4*)(sm + so_h + dst) = sh[i];
        *(uint4*)(sm + so_l + dst) = sl[i];
    }
}

// ---------------- small kernels ----------------------------------------------
__global__ void k_init(const float* __restrict__ u_in)
{
    int i = blockIdx.x * blockDim.x + threadIdx.x;
    int stride = gridDim.x * blockDim.x;
    for (int x = i; x < NN * D; x += stride) g_ebar[x] = 0.f;
    if (i < NN) g_indeg[i] = 0.f;
    if (i < NG) g_cntg[i] = 0.f;
    if (i < NG * D) { g_u[i] = u_in[i]; g_gsum_node[i] = 0.f; g_gsum_ebar[i] = 0.f; }
}
__global__ void k_hist(const int* __restrict__ ei, const int* __restrict__ batch)
{
    int i = blockIdx.x * blockDim.x + threadIdx.x;
    if (i < NE) atomicAdd(&g_indeg[ei[NE + i]], 1.f);
    if (i < NN) atomicAdd(&g_cntg[batch[i]], 1.f);
}
__global__ void k_zero_pass()
{
    int i = blockIdx.x * blockDim.x + threadIdx.x;
    int stride = gridDim.x * blockDim.x;
    for (int x = i; x < NN * D; x += stride) g_ebar[x] = 0.f;
    if (i < NG * D) { g_gsum_node[i] = 0.f; g_gsum_ebar[i] = 0.f; }
}
__global__ void k_wprep(const float* __restrict__ We_w, const float* __restrict__ Wn_w)
{
    int m = blockIdx.x, t = threadIdx.x;
    const float* W = (m == 0) ? We_w
                   : (m == 1) ? We_w + D * D
                   : (m == 2) ? We_w + 2 * D * D
                   : (m == 3) ? Wn_w
                              : Wn_w + D * D;
    uint4* ih = g_Wimg[m][0];
    uint4* il = g_Wimg[m][1];
    for (int g = t; g < 2048; g += 256) {
        int n = g >> 4, c8 = (g & 15) << 3;
        float f[8];
#pragma unroll
        for (int j = 0; j < 8; j++) f[j] = W[(c8 + j) * D + n];
        uint4 hi, lo;
        split8(f, hi, lo);
        ih[g] = hi;
        il[g] = lo;
    }
}
__global__ void k_uproj(const float* __restrict__ We_w, const float* __restrict__ We_b,
                        const float* __restrict__ Wn_w, const float* __restrict__ Wn_b)
{
    int g = blockIdx.x, j = threadIdx.x;
    __shared__ float us[D];
    us[j] = g_u[g * D + j];
    __syncthreads();
    float aE = We_b[j], aN = Wn_b[j];
#pragma unroll 4
    for (int k = 0; k < D; k++) {
        float uv = us[k];
        aE = fmaf(uv, We_w[(3 * D + k) * D + j], aE);
        aN = fmaf(uv, Wn_w[(2 * D + k) * D + j], aN);
    }
    g_uprojE[g * D + j] = aE;
    g_uprojN[g * D + j] = aN;
}

// ---------------- k_proj: NW1|NW2 = node @ [We1|We2] (128-row, occ1) ---------
__global__ void __launch_bounds__(256, 1) k_proj(const float* __restrict__ Nsrc)
{
    extern __shared__ char sm[];
    uint32_t smb = smem_to_u32(sm);
    int t = threadIdx.x, lane = t & 31, wid = t >> 5;
    int wm = wid >> 2, wn = wid & 3;
    int n0 = blockIdx.x * 128;

    copy_w128(sm, SO_W0H, SO_W0L, 0, t);   // We1
    copy_w128(sm, SO_W1H, SO_W1L, 1, t);   // We2
    for (int g = t; g < 2048; g += 256) {
        int r = g >> 4, c8 = (g & 15) << 3;
        int n = n0 + r;
        float f[8] = {0, 0, 0, 0, 0, 0, 0, 0};
        if (n < NN) { *(float4*)f = *(const float4*)(Nsrc + (size_t)n * D + c8);
                      *(float4*)(f + 4) = *(const float4*)(Nsrc + (size_t)n * D + c8 + 4); }
        uint4 hi, lo; split8(f, hi, lo);
        int off = r * LDKB + c8 * 2;
        *(uint4*)(sm + SO_AH + off) = hi;
        *(uint4*)(sm + SO_AL + off) = lo;
    }
    __syncthreads();

    float acc[4][4][4];
    // tile 0: node @ We1
    acc_zero(acc);
    mma_term(smb + SO_AH, smb + SO_W0H, acc, lane, wm, wn);
    mma_term(smb + SO_AH, smb + SO_W0L, acc, lane, wm, wn);
    mma_term(smb + SO_AL, smb + SO_W0H, acc, lane, wm, wn);
    __syncthreads();
    stage_acc((float*)(sm + SO_C2), acc, lane, wm, wn);
    __syncthreads();
    for (int r = wid * 16; r < wid * 16 + 16; r++) {   // row-per-warp store
        int n = n0 + r;
        if (n < NN) {
            float4 v = *(const float4*)((const float*)(sm + SO_C2) + r * LDC + lane * 4);
            *(float4*)(g_NW + (size_t)n * 256 + lane * 4) = v;
        }
    }
    // tile 1: node @ We2
    acc_zero(acc);
    mma_term(smb + SO_AH, smb + SO_W1H, acc, lane, wm, wn);
    mma_term(smb + SO_AH, smb + SO_W1L, acc, lane, wm, wn);
    mma_term(smb + SO_AL, smb + SO_W1H, acc, lane, wm, wn);
    __syncthreads();
    stage_acc((float*)(sm + SO_C), acc, lane, wm, wn);
    __syncthreads();
    for (int r = wid * 16; r < wid * 16 + 16; r++) {
        int n = n0 + r;
        if (n < NN) {
            float4 v = *(const float4*)((const float*)(sm + SO_C) + r * LDC + lane * 4);
            *(float4*)(g_NW + (size_t)n * 256 + 128 + lane * 4) = v;
        }
    }
}

// ---------------- k_edge: relu(e@We3 + NW1[src] + NW2[dst] + uprojE) ---------
__global__ void __launch_bounds__(128, 2) k_edge_tc(const float* __restrict__ Eattr,
                                                    const int* __restrict__ ei,
                                                    const int* __restrict__ batch, int last)
{
    extern __shared__ char sm[];
    uint32_t smb = smem_to_u32(sm);
    int t = threadIdx.x, lane = t & 31, wid = t >> 5;
    int wm = wid >> 1, wn = wid & 1;
    int e0 = blockIdx.x * 64;

    copy_w64(sm, 2, t);                      // We3
    for (int g = t; g < 1024; g += 128) {    // A = edge features (no guard: NE % 64 == 0)
        int r = g >> 4, c8 = (g & 15) << 3;
        float f[8];
        *(float4*)f       = *(const float4*)(Eattr + (size_t)(e0 + r) * D + c8);
        *(float4*)(f + 4) = *(const float4*)(Eattr + (size_t)(e0 + r) * D + c8 + 4);
        store_a64(sm, r, c8, f);
    }
    __syncthreads();

    float acc[2][8][4];
    acc_zero64(acc);
    mainloop64(smb, acc, lane, wm, wn);
    __syncthreads();
    stage64((float*)sm, acc, lane, wm, wn);  // overlays A region
    __syncthreads();

    for (int r = wid * 16; r < wid * 16 + 16; r++) {   // row-per-warp epilogue
        int e = e0 + r;
        int sN = ei[e], dN = ei[NE + e], gb = batch[sN];
        float4 c = *(const float4*)((const float*)sm + r * LDC + lane * 4);
        float4 a = *(const float4*)(g_NW + (size_t)sN * 256 + lane * 4);
        float4 b = *(const float4*)(g_NW + (size_t)dN * 256 + 128 + lane * 4);
        float4 u = *(const float4*)(g_uprojE + (size_t)gb * D + lane * 4);
        float y0 = fmaxf(c.x + a.x + b.x + u.x, 0.f);
        float y1 = fmaxf(c.y + a.y + b.y + u.y, 0.f);
        float y2 = fmaxf(c.z + a.z + b.z + u.z, 0.f);
        float y3 = fmaxf(c.w + a.w + b.w + u.w, 0.f);
        if (!last) *(float4*)(g_edge + (size_t)e * D + lane * 4) = make_float4(y0, y1, y2, y3);
        red_add_v4(g_ebar + (size_t)dN * D + lane * 4, y0, y1, y2, y3);
    }
}

// ---------------- k_node_a: tmp = (ebar * inv_deg) @ Wn2 (+ gsum_ebar) -------
__global__ void __launch_bounds__(128, 2) k_node_a(const int* __restrict__ batch)
{
    extern __shared__ char sm[];
    uint32_t smb = smem_to_u32(sm);
    int t = threadIdx.x, lane = t & 31, wid = t >> 5;
    int wm = wid >> 1, wn = wid & 1;
    int n0 = blockIdx.x * 64;

    copy_w64(sm, 4, t);                      // Wn2
    for (int g = t; g < 1024; g += 128) {
        int r = g >> 4, c8 = (g & 15) << 3;
        int n = n0 + r;
        float f[8] = {0, 0, 0, 0, 0, 0, 0, 0};
        if (n < NN) {
            float inv = 1.f / fmaxf(g_indeg[n], 1.f);
            float4 v0 = *(const float4*)(g_ebar + (size_t)n * D + c8);
            float4 v1 = *(const float4*)(g_ebar + (size_t)n * D + c8 + 4);
            f[0] = v0.x * inv; f[1] = v0.y * inv; f[2] = v0.z * inv; f[3] = v0.w * inv;
            f[4] = v1.x * inv; f[5] = v1.y * inv; f[6] = v1.z * inv; f[7] = v1.w * inv;
            float* pg = g_gsum_ebar + (size_t)batch[n] * D + c8;
            red_add_v4(pg,     f[0], f[1], f[2], f[3]);
            red_add_v4(pg + 4, f[4], f[5], f[6], f[7]);
        }
        store_a64(sm, r, c8, f);
    }
    __syncthreads();

    float acc[2][8][4];
    acc_zero64(acc);
    mainloop64(smb, acc, lane, wm, wn);
    __syncthreads();
    stage64((float*)sm, acc, lane, wm, wn);
    __syncthreads();

    for (int r = wid * 16; r < wid * 16 + 16; r++) {
        int n = n0 + r;
        if (n < NN) {
            float4 v = *(const float4*)((const float*)sm + r * LDC + lane * 4);
            *(float4*)(g_tmp + (size_t)n * D + lane * 4) = v;
        }
    }
}

// ---------------- k_node_b: relu(node@Wn1 + tmp + uprojN) --------------------
__global__ void __launch_bounds__(128, 2) k_node_b(const float* __restrict__ Nsrc,
                                                   const int* __restrict__ batch, int last)
{
    extern __shared__ char sm[];
    uint32_t smb = smem_to_u32(sm);
    int t = threadIdx.x, lane = t & 31, wid = t >> 5;
    int wm = wid >> 1, wn = wid & 1;
    int n0 = blockIdx.x * 64;

    copy_w64(sm, 3, t);                      // Wn1
    for (int g = t; g < 1024; g += 128) {
        int r = g >> 4, c8 = (g & 15) << 3;
        int n = n0 + r;
        float f[8] = {0, 0, 0, 0, 0, 0, 0, 0};
        if (n < NN) { *(float4*)f = *(const float4*)(Nsrc + (size_t)n * D + c8);
                      *(float4*)(f + 4) = *(const float4*)(Nsrc + (size_t)n * D + c8 + 4); }
        store_a64(sm, r, c8, f);
    }
    __syncthreads();

    float acc[2][8][4];
    acc_zero64(acc);
    mainloop64(smb, acc, lane, wm, wn);
    __syncthreads();
    stage64((float*)sm, acc, lane, wm, wn);
    __syncthreads();

    for (int r = wid * 16; r < wid * 16 + 16; r++) {
        int n = n0 + r;
        if (n < NN) {
            int gb = batch[n];
            float4 c = *(const float4*)((const float*)sm + r * LDC + lane * 4);
            float4 w = *(const float4*)(g_tmp + (size_t)n * D + lane * 4);
            float4 u = *(const float4*)(g_uprojN + (size_t)gb * D + lane * 4);
            float y0 = fmaxf(c.x + w.x + u.x, 0.f);
            float y1 = fmaxf(c.y + w.y + u.y, 0.f);
            float y2 = fmaxf(c.z + w.z + u.z, 0.f);
            float y3 = fmaxf(c.w + w.w + u.w, 0.f);
            if (!last) *(float4*)(g_node + (size_t)n * D + lane * 4) = make_float4(y0, y1, y2, y3);
            red_add_v4(g_gsum_node + (size_t)gb * D + lane * 4, y0, y1, y2, y3);
        }
    }
}

// ---------------- global update + next-pass u projections ---------------------
__global__ void k_global(const float* __restrict__ Wg_w, const float* __restrict__ Wg_b,
                         const float* __restrict__ We_w, const float* __restrict__ We_b,
                         const float* __restrict__ Wn_w, const float* __restrict__ Wn_b)
{
    int g = blockIdx.x, j = threadIdx.x;
    __shared__ float nm[D], em[D], uu[D], un[D];
    float inv = 1.f / fmaxf(g_cntg[g], 1.f);
    nm[j] = g_gsum_node[g * D + j] * inv;
    em[j] = g_gsum_ebar[g * D + j] * inv;
    uu[j] = g_u[g * D + j];
    __syncthreads();
    float acc = Wg_b[j];
#pragma unroll 4
    for (int k = 0; k < D; k++) {
        acc = fmaf(nm[k], Wg_w[k * D + j], acc);
        acc = fmaf(em[k], Wg_w[(D + k) * D + j], acc);
        acc = fmaf(uu[k], Wg_w[(2 * D + k) * D + j], acc);
    }
    float r = fmaxf(acc, 0.f);
    g_u[g * D + j] = r;
    un[j] = r;
    __syncthreads();
    float aE = We_b[j], aN = Wn_b[j];
#pragma unroll 4
    for (int k = 0; k < D; k++) {
        float uv = un[k];
        aE = fmaf(uv, We_w[(3 * D + k) * D + j], aE);
        aN = fmaf(uv, Wn_w[(2 * D + k) * D + j], aN);
    }
    g_uprojE[g * D + j] = aE;
    g_uprojN[g * D + j] = aN;
}

__global__ void k_readout(const float* __restrict__ lin_w, const float* __restrict__ lin_b,
                          float* __restrict__ out)
{
    int g = blockIdx.x, t = threadIdx.x;
    __shared__ float pooled[3 * D];
    float inv = 1.f / fmaxf(g_cntg[g], 1.f);
    pooled[t]         = g_gsum_node[g * D + t] * inv;
    pooled[D + t]     = g_gsum_ebar[g * D + t] * inv;
    pooled[2 * D + t] = g_u[g * D + t];
    __syncthreads();
    if (t < NCLS) {
        float acc = lin_b[t];
#pragma unroll 4
        for (int k = 0; k < 3 * D; k++) acc = fmaf(pooled[k], lin_w[k * NCLS + t], acc);
        out[g * NCLS + t] = acc;
    }
}

// ---------------- host launcher ----------------------------------------------
extern "C" void kernel_launch(void* const* d_in, const int* in_sizes, int n_in,
                              void* d_out, int out_size)
{
    const float* node_in = (const float*)d_in[0];
    const float* edge_in = (const float*)d_in[1];
    const float* u_in    = (const float*)d_in[2];
    const int*   ei      = (const int*)d_in[3];
    const int*   batch   = (const int*)d_in[4];
    const float* We_w = (const float*)d_in[5];
    const float* We_b = (const float*)d_in[6];
    const float* Wn_w = (const float*)d_in[7];
    const float* Wn_b = (const float*)d_in[8];
    const float* Wg_w = (const float*)d_in[9];
    const float* Wg_b = (const float*)d_in[10];
    const float* lin_w = (const float*)d_in[11];
    const float* lin_b = (const float*)d_in[12];
    float* out = (float*)d_out;

    float *p_node = nullptr, *p_edge = nullptr;
    cudaGetSymbolAddress((void**)&p_node, g_node);
    cudaGetSymbolAddress((void**)&p_edge, g_edge);

    cudaFuncSetAttribute(k_proj,    cudaFuncAttributeMaxDynamicSharedMemorySize, SM_BIG);
    cudaFuncSetAttribute(k_edge_tc, cudaFuncAttributeMaxDynamicSharedMemorySize, SM64);
    cudaFuncSetAttribute(k_node_a,  cudaFuncAttributeMaxDynamicSharedMemorySize, SM64);
    cudaFuncSetAttribute(k_node_b,  cudaFuncAttributeMaxDynamicSharedMemorySize, SM64);

    // launch order puts k_edge_tc at global launch index 5 (ncu -s 5 -c 1)
    k_init<<<1024, 256>>>(u_in);                       // 0
    k_hist<<<(NE + 255) / 256, 256>>>(ei, batch);      // 1
    k_wprep<<<5, 256>>>(We_w, Wn_w);                   // 2
    k_uproj<<<NG, D>>>(We_w, We_b, Wn_w, Wn_b);        // 3

    const float* nsrc = node_in;
    const float* esrc = edge_in;
    for (int p = 0; p < 3; p++) {
        int last = (p == 2);
        k_proj<<<NT_N, 256, SM_BIG>>>(nsrc);                      // 4 (p=0)
        k_edge_tc<<<NT_E, 128, SM64>>>(esrc, ei, batch, last);    // 5 (p=0)
        k_node_a<<<NT64_N, 128, SM64>>>(batch);
        k_node_b<<<NT64_N, 128, SM64>>>(nsrc, batch, last);
        k_global<<<NG, D>>>(Wg_w, Wg_b, We_w, We_b, Wn_w, Wn_b);
        if (p < 2) k_zero_pass<<<1024, 256>>>();
        nsrc = p_node;
        esrc = p_edge;
    }
    k_readout<<<NG, D>>>(lin_w, lin_b, out);
}